// round 11
// baseline (speedup 1.0000x reference)
#include <cuda_runtime.h>
#include <cuda_bf16.h>
#include <cuda_fp16.h>
#include <cstdint>

// Problem constants
#define NN    10000
#define EE    320000
#define BB    64
#define IN_C  128
#define EC    64
#define HID   256
#define MLPD  512
#define NCO   4
#define K1    320
#define K23   576
#define EPSV  1e-5f
#define MAXSZ 40.0f
#define PADROWS 128
#define LSTR  (HID * K23)   // per-layer B image stride (elements)

// ---------------- scratch ----------------
__device__ int   g_deg[NN];
__device__ int   g_off[NN + 2];
__device__ int   g_cur[NN];
__device__ int   g_src[EE];
__device__ int   g_eid[EE];
__device__ __align__(16) float g_Sea[NN * EC];
__device__ __align__(16) __half g_hp16[NN * HID];  // post-relu pre-BN activation (fp16)
__device__ __align__(16) __half g_x16[NN * IN_C];  // fp16 copy of input features
__device__ float g_stats3[3 * 2 * HID];
__device__ __align__(16) __half g_A16[(NN + PADROWS) * K23];  // fp16 A
__device__ __align__(16) __half g_Bhi[3 * LSTR];  // [layer][n 256][k K] fp16

// ---------------- helpers ----------------
__device__ __forceinline__ uint32_t smem_u32(const void* p) {
    uint32_t a;
    asm("{ .reg .u64 t; cvta.to.shared.u64 t, %1; cvt.u32.u64 %0, t; }" : "=r"(a) : "l"(p));
    return a;
}
__device__ __forceinline__ void ldsm4(uint32_t* r, uint32_t addr) {
    asm volatile("ldmatrix.sync.aligned.m8n8.x4.shared.b16 {%0,%1,%2,%3}, [%4];"
                 : "=r"(r[0]), "=r"(r[1]), "=r"(r[2]), "=r"(r[3]) : "r"(addr));
}
__device__ __forceinline__ void mma_f16(float* c, const uint32_t* a, const uint32_t* b) {
    asm volatile(
        "mma.sync.aligned.m16n8k16.row.col.f32.f16.f16.f32 "
        "{%0,%1,%2,%3}, {%4,%5,%6,%7}, {%8,%9}, {%0,%1,%2,%3};\n"
        : "+f"(c[0]), "+f"(c[1]), "+f"(c[2]), "+f"(c[3])
        : "r"(a[0]), "r"(a[1]), "r"(a[2]), "r"(a[3]), "r"(b[0]), "r"(b[1]));
}

// ---------------- init + x->fp16 + W prep (merged) ----------------
__global__ void init_kernel(const float* __restrict__ x, const float* __restrict__ W1,
                            const float* __restrict__ W2, const float* __restrict__ W3) {
    int i = blockIdx.x * blockDim.x + threadIdx.x;
    if (i < NN) g_deg[i] = 0;
    if (i < 3 * 2 * HID) g_stats3[i] = 0.f;
    __half z = __float2half(0.f);
    if (i < PADROWS * K1) g_A16[(size_t)NN * K1 + i] = z;
    if (i < PADROWS * K23) g_A16[(size_t)NN * K23 + i] = z;
    if (i < NN * IN_C) g_x16[i] = __float2half_rn(x[i]);
    // W images: B = W^T, [n][k] k-major
    if (i < HID * K1) {
        int n = i / K1, k = i - n * K1;
        g_Bhi[i] = __float2half_rn(W1[(size_t)k * HID + n]);
    }
    if (i < HID * K23) {
        int n = i / K23, k = i - n * K23;
        g_Bhi[LSTR + i] = __float2half_rn(W2[(size_t)k * HID + n]);
        g_Bhi[2 * LSTR + i] = __float2half_rn(W3[(size_t)k * HID + n]);
    }
}

// ---------------- CSR build ----------------
__global__ void hist_kernel(const int* __restrict__ ei) {
    int e = (blockIdx.x * blockDim.x + threadIdx.x) * 4;
#pragma unroll
    for (int k = 0; k < 4; k++)
        if (e + k < EE) atomicAdd(&g_deg[ei[EE + e + k]], 1);
}

__global__ void scan_kernel() {
    const int CH = 10;
    int tid = threadIdx.x;
    int base = tid * CH;
    int local[CH];
    int s = 0;
#pragma unroll
    for (int i = 0; i < CH; i++) {
        int idx = base + i;
        int v = (idx < NN) ? g_deg[idx] : 0;
        local[i] = s;
        s += v;
    }
    __shared__ int sh[1024];
    sh[tid] = s;
    __syncthreads();
    for (int d = 1; d < 1024; d <<= 1) {
        int t = (tid >= d) ? sh[tid - d] : 0;
        __syncthreads();
        sh[tid] += t;
        __syncthreads();
    }
    int excl = sh[tid] - s;
#pragma unroll
    for (int i = 0; i < CH; i++) {
        int idx = base + i;
        if (idx < NN) {
            int o = excl + local[i];
            g_off[idx] = o;
            g_cur[idx] = o;
        }
    }
    if (tid == 0) { g_off[NN] = EE; g_off[NN + 1] = EE; }
}

__global__ void fill_kernel(const int* __restrict__ ei) {
    int e = (blockIdx.x * blockDim.x + threadIdx.x) * 4;
#pragma unroll
    for (int k = 0; k < 4; k++) {
        int ee = e + k;
        if (ee < EE) {
            int s = ei[ee];
            int d = ei[EE + ee];
            int pos = atomicAdd(&g_cur[d], 1);
            g_src[pos] = s;
            g_eid[pos] = ee;
        }
    }
}

// ---------------- layer-1 aggregation + fused edge-attr sums + fp16 A (R9 structure) ----------------
__global__ void aggprep1_kernel(const float* __restrict__ ea) {
    int v = blockIdx.x;
    int t = threadIdx.x;  // 128
    int s0 = g_off[v], s1 = g_off[v + 1];
    float self = __half2float(g_x16[(size_t)v * IN_C + t]);
    float acc = self;
    float aea = 1.0f;  // self-loop edge attr = 1.0
    int j = s0;
    for (; j + 4 <= s1; j += 4) {
        int a = g_src[j], b = g_src[j + 1], c = g_src[j + 2], d = g_src[j + 3];
        acc += __half2float(g_x16[(size_t)a * IN_C + t]) +
               __half2float(g_x16[(size_t)b * IN_C + t]) +
               __half2float(g_x16[(size_t)c * IN_C + t]) +
               __half2float(g_x16[(size_t)d * IN_C + t]);
        if (t < EC) {
            int e0 = g_eid[j], e1 = g_eid[j + 1], e2 = g_eid[j + 2], e3 = g_eid[j + 3];
            aea += ea[(size_t)e0 * EC + t] + ea[(size_t)e1 * EC + t] +
                   ea[(size_t)e2 * EC + t] + ea[(size_t)e3 * EC + t];
        }
    }
    for (; j < s1; j++) {
        acc += __half2float(g_x16[(size_t)g_src[j] * IN_C + t]);
        if (t < EC) aea += ea[(size_t)g_eid[j] * EC + t];
    }

    float degf = (float)(s1 - s0 + 1);
    size_t rb = (size_t)v * K1;
    g_A16[rb + t] = __float2half_rn(degf * self);
    g_A16[rb + IN_C + t] = __float2half_rn(acc);
    if (t < EC) {
        g_Sea[v * EC + t] = aea;
        g_A16[rb + 2 * IN_C + t] = __float2half_rn(aea);
    }
}

// ---------------- layers 2/3: fused BN + relu + aggregation + fp16 A (R9 structure) ----------------
template <bool WRITE_SEA>
__global__ void aggprep23_kernel(int statsLayer, const float* __restrict__ gamma,
                                 const float* __restrict__ beta) {
    int v = blockIdx.x;
    int t = threadIdx.x;  // 256
    const float invN = 1.0f / (float)NN;
    float mu = g_stats3[statsLayer * 512 + t] * invN;
    float var = g_stats3[statsLayer * 512 + HID + t] * invN - mu * mu;
    float rs = rsqrtf(var + EPSV);
    float sc = gamma[t] * rs;
    float off = beta[t] - mu * sc;

    int s0 = g_off[v], s1 = g_off[v + 1];
    const __half* __restrict__ hp = g_hp16;
    float selfv = fmaxf(__half2float(hp[(size_t)v * HID + t]) * sc + off, 0.f);
    float acc = selfv;
    int j = s0;
    for (; j + 4 <= s1; j += 4) {
        int a = g_src[j], b = g_src[j + 1], c = g_src[j + 2], d = g_src[j + 3];
        acc += fmaxf(__half2float(hp[(size_t)a * HID + t]) * sc + off, 0.f)
             + fmaxf(__half2float(hp[(size_t)b * HID + t]) * sc + off, 0.f)
             + fmaxf(__half2float(hp[(size_t)c * HID + t]) * sc + off, 0.f)
             + fmaxf(__half2float(hp[(size_t)d * HID + t]) * sc + off, 0.f);
    }
    for (; j < s1; j++)
        acc += fmaxf(__half2float(hp[(size_t)g_src[j] * HID + t]) * sc + off, 0.f);

    float degf = (float)(s1 - s0 + 1);
    size_t rb = (size_t)v * K23;
    g_A16[rb + t] = __float2half_rn(degf * selfv);
    g_A16[rb + HID + t] = __float2half_rn(acc);
    if (WRITE_SEA && t < EC)
        g_A16[rb + 2 * HID + t] = __float2half_rn(g_Sea[v * EC + t]);
}

// ---------------- fp16 single-pass HMMA GEMM: g_hp16 = relu(A @ W + deg*b), fused fp32 stats ----------------
// BM=128, BN=64, BK=32. 256 threads, warps 4x2 (warp tile 32x32).
// SMEM stage: A 8K | B 4K = 12K, double-buffered = 24K dyn.
template <int K, int NCH>
__global__ __launch_bounds__(256, 2) void f16gemm_kernel(int layer,
                                                         const float* __restrict__ bias) {
    extern __shared__ __align__(16) char smbuf[];
    const int STG = 12288;
    __shared__ float s_bias[64], s_deg[128], s_sum[64], s_sq[64];

    int tid = threadIdx.x;
    int lane = tid & 31;
    int wid = tid >> 5;
    int wm = wid >> 1;   // 0..3
    int wn = wid & 1;    // 0..1
    int rowBase = blockIdx.y * 128;
    int colBase = blockIdx.x * 64;

    if (tid < 128) {
        int r = rowBase + tid;
        s_deg[tid] = (r < NN) ? (float)(g_off[r + 1] - g_off[r] + 1) : 0.f;
    }
    if (tid < 64) {
        s_bias[tid] = bias[colBase + tid];
        s_sum[tid] = 0.f;
        s_sq[tid] = 0.f;
    }

    uint32_t smb = smem_u32(smbuf);

    const __half* __restrict__ Ag = g_A16;
    const __half* __restrict__ Bg = g_Bhi + (size_t)layer * LSTR;

    // A load map: thread -> row = tid/2, 2 segs (16 halves) starting at (tid&1)*16
    int arow = tid >> 1;
    int at2 = tid & 1;
    size_t aoffBase = (size_t)(rowBase + arow) * K + at2 * 16;
    uint32_t asw0 = (uint32_t)arow * 64 + (((at2 * 2) ^ ((arow >> 1) & 3)) << 4);
    uint32_t asw1 = (uint32_t)arow * 64 + (((at2 * 2 + 1) ^ ((arow >> 1) & 3)) << 4);
    // B load map: thread -> row(n) = tid/4, seg = tid&3
    int brow = tid >> 2;
    int bseg = tid & 3;
    size_t boffBase = (size_t)(colBase + brow) * K + bseg * 8;
    uint32_t bsw = 8192u + (uint32_t)brow * 64 + ((bseg ^ ((brow >> 1) & 3)) << 4);

    float acc[2][4][4];
#pragma unroll
    for (int i = 0; i < 2; i++)
#pragma unroll
        for (int j = 0; j < 4; j++)
#pragma unroll
            for (int q = 0; q < 4; q++) acc[i][j][q] = 0.f;

    // prologue: chunk 0 -> buf0
    {
        uint4 a0 = *(const uint4*)(Ag + aoffBase);
        uint4 a1 = *(const uint4*)(Ag + aoffBase + 8);
        uint4 b0 = *(const uint4*)(Bg + boffBase);
        *(uint4*)(smbuf + asw0) = a0;
        *(uint4*)(smbuf + asw1) = a1;
        *(uint4*)(smbuf + bsw) = b0;
    }
    __syncthreads();

    // frag address components
    int ra = wm * 32 + (lane & 7) + ((lane >> 3) & 1) * 8;
    int rb = wn * 32 + (lane & 7) + ((lane >> 4) & 1) * 8;

    for (int c = 0; c < NCH; c++) {
        uint4 na0, na1, nb0;
        if (c + 1 < NCH) {
            size_t ao = aoffBase + (size_t)(c + 1) * 32;
            size_t bo = boffBase + (size_t)(c + 1) * 32;
            na0 = *(const uint4*)(Ag + ao);
            na1 = *(const uint4*)(Ag + ao + 8);
            nb0 = *(const uint4*)(Bg + bo);
        }

        uint32_t base = smb + (uint32_t)(c & 1) * STG;
#pragma unroll
        for (int ks = 0; ks < 2; ks++) {
            int sa = ks * 2 + (lane >> 4);
            int sb = ks * 2 + ((lane >> 3) & 1);
            uint32_t ah[2][4];
#pragma unroll
            for (int i = 0; i < 2; i++) {
                int rr = ra + i * 16;
                uint32_t off = (uint32_t)rr * 64 + ((sa ^ ((rr >> 1) & 3)) << 4);
                ldsm4(ah[i], base + off);
            }
            uint32_t bh[4][2];
#pragma unroll
            for (int p = 0; p < 2; p++) {
                int rr = rb + p * 16;
                uint32_t off = (uint32_t)rr * 64 + ((sb ^ ((rr >> 1) & 3)) << 4);
                uint32_t t4[4];
                ldsm4(t4, base + 8192 + off);
                bh[2 * p][0] = t4[0]; bh[2 * p][1] = t4[1];
                bh[2 * p + 1][0] = t4[2]; bh[2 * p + 1][1] = t4[3];
            }
#pragma unroll
            for (int i = 0; i < 2; i++)
#pragma unroll
                for (int j = 0; j < 4; j++)
                    mma_f16(acc[i][j], ah[i], bh[j]);
        }

        if (c + 1 < NCH) {
            char* d = smbuf + ((c + 1) & 1) * STG;
            *(uint4*)(d + asw0) = na0;
            *(uint4*)(d + asw1) = na1;
            *(uint4*)(d + bsw) = nb0;
            __syncthreads();
        }
    }

    // ---------- epilogue: bias + relu + fp16 store + fp32 stats ----------
    float ss0[4], ss1[4], qq0[4], qq1[4];
#pragma unroll
    for (int j = 0; j < 4; j++) { ss0[j] = ss1[j] = qq0[j] = qq1[j] = 0.f; }

    int mb = rowBase + wm * 32 + (lane >> 2);
#pragma unroll
    for (int i = 0; i < 2; i++) {
        int m0 = mb + i * 16;
        int m1 = m0 + 8;
        bool v0 = m0 < NN, v1 = m1 < NN;
        float d0 = s_deg[m0 - rowBase];
        float d1 = s_deg[m1 - rowBase];
#pragma unroll
        for (int j = 0; j < 4; j++) {
            int cl = wn * 32 + j * 8 + (lane & 3) * 2;
            float b0 = s_bias[cl], b1 = s_bias[cl + 1];
            float x0 = fmaxf(acc[i][j][0] + d0 * b0, 0.f);
            float x1 = fmaxf(acc[i][j][1] + d0 * b1, 0.f);
            float x2 = fmaxf(acc[i][j][2] + d1 * b0, 0.f);
            float x3 = fmaxf(acc[i][j][3] + d1 * b1, 0.f);
            if (v0) *(__half2*)&g_hp16[(size_t)m0 * HID + colBase + cl] = __floats2half2_rn(x0, x1);
            if (v1) *(__half2*)&g_hp16[(size_t)m1 * HID + colBase + cl] = __floats2half2_rn(x2, x3);
            float m00 = v0 ? x0 : 0.f, m01 = v0 ? x1 : 0.f;
            float m10 = v1 ? x2 : 0.f, m11 = v1 ? x3 : 0.f;
            ss0[j] += m00 + m10;
            ss1[j] += m01 + m11;
            qq0[j] += m00 * m00 + m10 * m10;
            qq1[j] += m01 * m01 + m11 * m11;
        }
    }
#pragma unroll
    for (int j = 0; j < 4; j++) {
#pragma unroll
        for (int o = 4; o < 32; o <<= 1) {
            ss0[j] += __shfl_xor_sync(0xffffffffu, ss0[j], o);
            ss1[j] += __shfl_xor_sync(0xffffffffu, ss1[j], o);
            qq0[j] += __shfl_xor_sync(0xffffffffu, qq0[j], o);
            qq1[j] += __shfl_xor_sync(0xffffffffu, qq1[j], o);
        }
        if (lane < 4) {
            int cl = wn * 32 + j * 8 + lane * 2;
            atomicAdd(&s_sum[cl], ss0[j]);
            atomicAdd(&s_sum[cl + 1], ss1[j]);
            atomicAdd(&s_sq[cl], qq0[j]);
            atomicAdd(&s_sq[cl + 1], qq1[j]);
        }
    }
    __syncthreads();
    if (tid < 64) {
        atomicAdd(&g_stats3[layer * 512 + colBase + tid], s_sum[tid]);
        atomicAdd(&g_stats3[layer * 512 + HID + colBase + tid], s_sq[tid]);
    }
}

// ---------------- fused layer-3 BN + pooling + MLP ----------------
__device__ __forceinline__ int lower_bound_dev(const int* a, int n, int key) {
    int lo = 0, hi = n;
    while (lo < hi) {
        int m = (lo + hi) >> 1;
        if (a[m] < key) lo = m + 1; else hi = m;
    }
    return lo;
}

__global__ __launch_bounds__(512) void mlp_kernel(const int* __restrict__ batch,
                                                  const float* __restrict__ neighbor,
                                                  const float* __restrict__ g3,
                                                  const float* __restrict__ be3,
                                                  const float* __restrict__ fc1w,
                                                  const float* __restrict__ fc1b,
                                                  const float* __restrict__ fc2w,
                                                  const float* __restrict__ fc2b,
                                                  float* __restrict__ out) {
    const int ZD = HID + 1 + IN_C;  // 385
    __shared__ float z[ZD];
    __shared__ float part[512];
    __shared__ float red[NCO];
    int b = blockIdx.x;
    int t = threadIdx.x;

    int lo = lower_bound_dev(batch, NN, b);
    int hi = lower_bound_dev(batch, NN, b + 1);

    {
        int c = t & 255;
        int half = t >> 8;
        const float invN = 1.0f / (float)NN;
        float mu = g_stats3[2 * 512 + c] * invN;
        float var = g_stats3[2 * 512 + HID + c] * invN - mu * mu;
        float rs = rsqrtf(var + EPSV);
        float sc = g3[c] * rs;
        float off = be3[c] - mu * sc;
        float s = 0.f;
        for (int r = lo + half; r < hi; r += 2)
            s += fmaxf(__half2float(g_hp16[(size_t)r * HID + c]) * sc + off, 0.f);
        part[t] = s;
    }
    __syncthreads();
    if (t < HID) z[t] = part[t] + part[t + 256];
    else if (t == HID) z[HID] = (float)(hi - lo) / MAXSZ;
    else if (t > HID && t < HID + 1 + IN_C + 1) {
        int k = t - HID - 1;
        if (k < IN_C) z[HID + 1 + k] = neighbor[b * IN_C + k];
    }
    if (t < NCO) red[t] = fc2b[t];
    __syncthreads();

    float acc = fc1b[t];
#pragma unroll 4
    for (int k = 0; k < ZD; k++) acc += z[k] * fc1w[k * MLPD + t];
    float h1 = fmaxf(acc, 0.f);

    float4 w4 = *(const float4*)&fc2w[t * NCO];
    float p0 = h1 * w4.x, p1 = h1 * w4.y, p2 = h1 * w4.z, p3 = h1 * w4.w;
#pragma unroll
    for (int o = 16; o >= 1; o >>= 1) {
        p0 += __shfl_xor_sync(0xffffffffu, p0, o);
        p1 += __shfl_xor_sync(0xffffffffu, p1, o);
        p2 += __shfl_xor_sync(0xffffffffu, p2, o);
        p3 += __shfl_xor_sync(0xffffffffu, p3, o);
    }
    if ((t & 31) == 0) {
        atomicAdd(&red[0], p0);
        atomicAdd(&red[1], p1);
        atomicAdd(&red[2], p2);
        atomicAdd(&red[3], p3);
    }
    __syncthreads();
    if (t < NCO) out[b * NCO + t] = red[t];
}

// ---------------- launch ----------------
extern "C" void kernel_launch(void* const* d_in, const int* in_sizes, int n_in,
                              void* d_out, int out_size) {
    const float* x        = (const float*)d_in[0];
    const int*   ei       = (const int*)d_in[1];
    const float* ea       = (const float*)d_in[2];
    const int*   batch    = (const int*)d_in[3];
    const float* neighbor = (const float*)d_in[4];
    const float* W1  = (const float*)d_in[5];
    const float* b1  = (const float*)d_in[6];
    const float* g1  = (const float*)d_in[7];
    const float* be1 = (const float*)d_in[8];
    const float* W2  = (const float*)d_in[9];
    const float* b2  = (const float*)d_in[10];
    const float* g2  = (const float*)d_in[11];
    const float* be2 = (const float*)d_in[12];
    const float* W3  = (const float*)d_in[13];
    const float* b3  = (const float*)d_in[14];
    const float* g3  = (const float*)d_in[15];
    const float* be3 = (const float*)d_in[16];
    const float* fc1w = (const float*)d_in[17];
    const float* fc1b = (const float*)d_in[18];
    const float* fc2w = (const float*)d_in[19];
    const float* fc2b = (const float*)d_in[20];
    float* out = (float*)d_out;

    // init + x16 + W images (NN*IN_C = 1.28M dominates the grid)
    init_kernel<<<(NN * IN_C + 255) / 256, 256>>>(x, W1, W2, W3);
    hist_kernel<<<(EE / 4 + 255) / 256, 256>>>(ei);
    scan_kernel<<<1, 1024>>>();
    fill_kernel<<<(EE / 4 + 255) / 256, 256>>>(ei);

    dim3 gg(4, 79);
    const size_t dsm = 24576;   // 2 x 12K stages

    // layer 1
    aggprep1_kernel<<<NN, IN_C>>>(ea);
    f16gemm_kernel<K1, 10><<<gg, 256, dsm>>>(0, b1);

    // layer 2
    aggprep23_kernel<true><<<NN, HID>>>(0, g1, be1);
    f16gemm_kernel<K23, 18><<<gg, 256, dsm>>>(1, b2);

    // layer 3
    aggprep23_kernel<false><<<NN, HID>>>(1, g2, be2);
    f16gemm_kernel<K23, 18><<<gg, 256, dsm>>>(2, b3);

    // layer-3 BN + pooling + MLP
    mlp_kernel<<<BB, MLPD>>>(batch, neighbor, g3, be3, fc1w, fc1b, fc2w, fc2b, out);
}

// round 12
// speedup vs baseline: 1.0406x; 1.0406x over previous
#include <cuda_runtime.h>
#include <cuda_bf16.h>
#include <cuda_fp16.h>
#include <cstdint>

// Problem constants
#define NN    10000
#define EE    320000
#define BB    64
#define IN_C  128
#define EC    64
#define HID   256
#define MLPD  512
#define NCO   4
#define K1    320
#define K23   576
#define EPSV  1e-5f
#define MAXSZ 40.0f
#define PADROWS 128
#define LSTR  (HID * K23)   // per-layer B image stride (elements)

// ---------------- scratch ----------------
__device__ int   g_deg[NN];
__device__ int   g_off[NN + 2];
__device__ int   g_cur[NN];
__device__ int   g_src[EE];
__device__ int   g_eid[EE];
__device__ __align__(16) float g_Sea[NN * EC];
__device__ __align__(16) __half g_hp16[NN * HID];  // post-relu pre-BN activation (fp16)
__device__ __align__(16) __half g_x16[NN * IN_C];  // fp16 copy of input features
__device__ float g_stats3[3 * 2 * HID];
__device__ __align__(16) __half g_A16[(NN + PADROWS) * K23];  // fp16 A
__device__ __align__(16) __half g_Bhi[3 * LSTR];  // [layer][n 256][k K] fp16

// ---------------- helpers ----------------
__device__ __forceinline__ uint32_t smem_u32(const void* p) {
    uint32_t a;
    asm("{ .reg .u64 t; cvta.to.shared.u64 t, %1; cvt.u32.u64 %0, t; }" : "=r"(a) : "l"(p));
    return a;
}
__device__ __forceinline__ void ldsm4(uint32_t* r, uint32_t addr) {
    asm volatile("ldmatrix.sync.aligned.m8n8.x4.shared.b16 {%0,%1,%2,%3}, [%4];"
                 : "=r"(r[0]), "=r"(r[1]), "=r"(r[2]), "=r"(r[3]) : "r"(addr));
}
__device__ __forceinline__ void mma_f16(float* c, const uint32_t* a, const uint32_t* b) {
    asm volatile(
        "mma.sync.aligned.m16n8k16.row.col.f32.f16.f16.f32 "
        "{%0,%1,%2,%3}, {%4,%5,%6,%7}, {%8,%9}, {%0,%1,%2,%3};\n"
        : "+f"(c[0]), "+f"(c[1]), "+f"(c[2]), "+f"(c[3])
        : "r"(a[0]), "r"(a[1]), "r"(a[2]), "r"(a[3]), "r"(b[0]), "r"(b[1]));
}

// ---------------- init + x->fp16 + W prep (merged) ----------------
__global__ void init_kernel(const float* __restrict__ x, const float* __restrict__ W1,
                            const float* __restrict__ W2, const float* __restrict__ W3) {
    int i = blockIdx.x * blockDim.x + threadIdx.x;
    if (i < NN) g_deg[i] = 0;
    if (i < 3 * 2 * HID) g_stats3[i] = 0.f;
    __half z = __float2half(0.f);
    if (i < PADROWS * K1) g_A16[(size_t)NN * K1 + i] = z;
    if (i < PADROWS * K23) g_A16[(size_t)NN * K23 + i] = z;
    if (i < NN * IN_C) g_x16[i] = __float2half_rn(x[i]);
    // W images: B = W^T, [n][k] k-major
    if (i < HID * K1) {
        int n = i / K1, k = i - n * K1;
        g_Bhi[i] = __float2half_rn(W1[(size_t)k * HID + n]);
    }
    if (i < HID * K23) {
        int n = i / K23, k = i - n * K23;
        g_Bhi[LSTR + i] = __float2half_rn(W2[(size_t)k * HID + n]);
        g_Bhi[2 * LSTR + i] = __float2half_rn(W3[(size_t)k * HID + n]);
    }
}

// ---------------- CSR build ----------------
__global__ void hist_kernel(const int* __restrict__ ei) {
    int e = (blockIdx.x * blockDim.x + threadIdx.x) * 4;
#pragma unroll
    for (int k = 0; k < 4; k++)
        if (e + k < EE) atomicAdd(&g_deg[ei[EE + e + k]], 1);
}

__global__ void scan_kernel() {
    const int CH = 10;
    int tid = threadIdx.x;
    int base = tid * CH;
    int local[CH];
    int s = 0;
#pragma unroll
    for (int i = 0; i < CH; i++) {
        int idx = base + i;
        int v = (idx < NN) ? g_deg[idx] : 0;
        local[i] = s;
        s += v;
    }
    __shared__ int sh[1024];
    sh[tid] = s;
    __syncthreads();
    for (int d = 1; d < 1024; d <<= 1) {
        int t = (tid >= d) ? sh[tid - d] : 0;
        __syncthreads();
        sh[tid] += t;
        __syncthreads();
    }
    int excl = sh[tid] - s;
#pragma unroll
    for (int i = 0; i < CH; i++) {
        int idx = base + i;
        if (idx < NN) {
            int o = excl + local[i];
            g_off[idx] = o;
            g_cur[idx] = o;
        }
    }
    if (tid == 0) { g_off[NN] = EE; g_off[NN + 1] = EE; }
}

__global__ void fill_kernel(const int* __restrict__ ei) {
    int e = (blockIdx.x * blockDim.x + threadIdx.x) * 4;
#pragma unroll
    for (int k = 0; k < 4; k++) {
        int ee = e + k;
        if (ee < EE) {
            int s = ei[ee];
            int d = ei[EE + ee];
            int pos = atomicAdd(&g_cur[d], 1);
            g_src[pos] = s;
            g_eid[pos] = ee;
        }
    }
}

// ---------------- layer-1: x gather (half2, warps 0-1) + ea gather (warps 2-3) ----------------
__global__ void aggprep1_kernel(const float* __restrict__ ea) {
    int v = blockIdx.x;
    int t = threadIdx.x;  // 128
    int s0 = g_off[v], s1 = g_off[v + 1];

    if (t < 64) {
        // gather x as half2: cols [2t, 2t+1]
        const __half2* __restrict__ x2 = (const __half2*)g_x16;  // row stride 64
        float2 f = __half22float2(x2[(size_t)v * 64 + t]);
        float a0 = f.x, a1 = f.y;
        int j = s0;
        for (; j + 4 <= s1; j += 4) {
            int ia = g_src[j], ib = g_src[j + 1], ic = g_src[j + 2], id = g_src[j + 3];
            float2 fa = __half22float2(x2[(size_t)ia * 64 + t]);
            float2 fb = __half22float2(x2[(size_t)ib * 64 + t]);
            float2 fc = __half22float2(x2[(size_t)ic * 64 + t]);
            float2 fd = __half22float2(x2[(size_t)id * 64 + t]);
            a0 += fa.x + fb.x + fc.x + fd.x;
            a1 += fa.y + fb.y + fc.y + fd.y;
        }
        for (; j < s1; j++) {
            float2 fa = __half22float2(x2[(size_t)g_src[j] * 64 + t]);
            a0 += fa.x;
            a1 += fa.y;
        }
        float degf = (float)(s1 - s0 + 1);
        __half2* Arow2 = (__half2*)(g_A16 + (size_t)v * K1);
        Arow2[t] = __floats2half2_rn(degf * f.x, degf * f.y);
        Arow2[64 + t] = __floats2half2_rn(a0, a1);
    } else {
        // gather edge attrs: col c
        int c = t - 64;
        float aea = 1.0f;  // self-loop edge attr = 1.0
        int j = s0;
        for (; j + 4 <= s1; j += 4) {
            int e0 = g_eid[j], e1 = g_eid[j + 1], e2 = g_eid[j + 2], e3 = g_eid[j + 3];
            aea += ea[(size_t)e0 * EC + c] + ea[(size_t)e1 * EC + c] +
                   ea[(size_t)e2 * EC + c] + ea[(size_t)e3 * EC + c];
        }
        for (; j < s1; j++) aea += ea[(size_t)g_eid[j] * EC + c];
        g_Sea[v * EC + c] = aea;
        g_A16[(size_t)v * K1 + 2 * IN_C + c] = __float2half_rn(aea);
    }
}

// ---------------- layers 2/3: fused BN + relu + half2 gather aggregation ----------------
template <bool WRITE_SEA>
__global__ void aggprep23_kernel(int statsLayer, const float* __restrict__ gamma,
                                 const float* __restrict__ beta) {
    int v = blockIdx.x;
    int t = threadIdx.x;  // 128; cols 2t, 2t+1
    int c0 = 2 * t, c1 = c0 + 1;
    const float invN = 1.0f / (float)NN;
    float mu0 = g_stats3[statsLayer * 512 + c0] * invN;
    float var0 = g_stats3[statsLayer * 512 + HID + c0] * invN - mu0 * mu0;
    float sc0 = gamma[c0] * rsqrtf(var0 + EPSV);
    float off0 = beta[c0] - mu0 * sc0;
    float mu1 = g_stats3[statsLayer * 512 + c1] * invN;
    float var1 = g_stats3[statsLayer * 512 + HID + c1] * invN - mu1 * mu1;
    float sc1 = gamma[c1] * rsqrtf(var1 + EPSV);
    float off1 = beta[c1] - mu1 * sc1;

    const __half2* __restrict__ hp2 = (const __half2*)g_hp16;  // row stride 128
    int s0 = g_off[v], s1 = g_off[v + 1];
    float2 f = __half22float2(hp2[(size_t)v * 128 + t]);
    float sv0 = fmaxf(f.x * sc0 + off0, 0.f);
    float sv1 = fmaxf(f.y * sc1 + off1, 0.f);
    float a0 = sv0, a1 = sv1;
    int j = s0;
    for (; j + 4 <= s1; j += 4) {
        int ia = g_src[j], ib = g_src[j + 1], ic = g_src[j + 2], id = g_src[j + 3];
        float2 fa = __half22float2(hp2[(size_t)ia * 128 + t]);
        float2 fb = __half22float2(hp2[(size_t)ib * 128 + t]);
        float2 fc = __half22float2(hp2[(size_t)ic * 128 + t]);
        float2 fd = __half22float2(hp2[(size_t)id * 128 + t]);
        a0 += fmaxf(fa.x * sc0 + off0, 0.f) + fmaxf(fb.x * sc0 + off0, 0.f) +
              fmaxf(fc.x * sc0 + off0, 0.f) + fmaxf(fd.x * sc0 + off0, 0.f);
        a1 += fmaxf(fa.y * sc1 + off1, 0.f) + fmaxf(fb.y * sc1 + off1, 0.f) +
              fmaxf(fc.y * sc1 + off1, 0.f) + fmaxf(fd.y * sc1 + off1, 0.f);
    }
    for (; j < s1; j++) {
        float2 fa = __half22float2(hp2[(size_t)g_src[j] * 128 + t]);
        a0 += fmaxf(fa.x * sc0 + off0, 0.f);
        a1 += fmaxf(fa.y * sc1 + off1, 0.f);
    }

    float degf = (float)(s1 - s0 + 1);
    __half2* Arow2 = (__half2*)(g_A16 + (size_t)v * K23);
    Arow2[t] = __floats2half2_rn(degf * sv0, degf * sv1);
    Arow2[128 + t] = __floats2half2_rn(a0, a1);
    if (WRITE_SEA && t < 32)
        Arow2[256 + t] = __floats2half2_rn(g_Sea[v * EC + 2 * t], g_Sea[v * EC + 2 * t + 1]);
}

// ---------------- fp16 single-pass HMMA GEMM: g_hp16 = relu(A @ W + deg*b), fused fp32 stats ----------------
// BM=128, BN=64, BK=32. 256 threads, warps 4x2 (warp tile 32x32).
// SMEM stage: A 8K | B 4K = 12K, double-buffered = 24K dyn.
template <int K, int NCH>
__global__ __launch_bounds__(256, 2) void f16gemm_kernel(int layer,
                                                         const float* __restrict__ bias) {
    extern __shared__ __align__(16) char smbuf[];
    const int STG = 12288;
    __shared__ float s_bias[64], s_deg[128], s_sum[64], s_sq[64];

    int tid = threadIdx.x;
    int lane = tid & 31;
    int wid = tid >> 5;
    int wm = wid >> 1;   // 0..3
    int wn = wid & 1;    // 0..1
    int rowBase = blockIdx.y * 128;
    int colBase = blockIdx.x * 64;

    if (tid < 128) {
        int r = rowBase + tid;
        s_deg[tid] = (r < NN) ? (float)(g_off[r + 1] - g_off[r] + 1) : 0.f;
    }
    if (tid < 64) {
        s_bias[tid] = bias[colBase + tid];
        s_sum[tid] = 0.f;
        s_sq[tid] = 0.f;
    }

    uint32_t smb = smem_u32(smbuf);

    const __half* __restrict__ Ag = g_A16;
    const __half* __restrict__ Bg = g_Bhi + (size_t)layer * LSTR;

    // A load map: thread -> row = tid/2, 2 segs (16 halves) starting at (tid&1)*16
    int arow = tid >> 1;
    int at2 = tid & 1;
    size_t aoffBase = (size_t)(rowBase + arow) * K + at2 * 16;
    uint32_t asw0 = (uint32_t)arow * 64 + (((at2 * 2) ^ ((arow >> 1) & 3)) << 4);
    uint32_t asw1 = (uint32_t)arow * 64 + (((at2 * 2 + 1) ^ ((arow >> 1) & 3)) << 4);
    // B load map: thread -> row(n) = tid/4, seg = tid&3
    int brow = tid >> 2;
    int bseg = tid & 3;
    size_t boffBase = (size_t)(colBase + brow) * K + bseg * 8;
    uint32_t bsw = 8192u + (uint32_t)brow * 64 + ((bseg ^ ((brow >> 1) & 3)) << 4);

    float acc[2][4][4];
#pragma unroll
    for (int i = 0; i < 2; i++)
#pragma unroll
        for (int j = 0; j < 4; j++)
#pragma unroll
            for (int q = 0; q < 4; q++) acc[i][j][q] = 0.f;

    // prologue: chunk 0 -> buf0
    {
        uint4 a0 = *(const uint4*)(Ag + aoffBase);
        uint4 a1 = *(const uint4*)(Ag + aoffBase + 8);
        uint4 b0 = *(const uint4*)(Bg + boffBase);
        *(uint4*)(smbuf + asw0) = a0;
        *(uint4*)(smbuf + asw1) = a1;
        *(uint4*)(smbuf + bsw) = b0;
    }
    __syncthreads();

    // frag address components
    int ra = wm * 32 + (lane & 7) + ((lane >> 3) & 1) * 8;
    int rb = wn * 32 + (lane & 7) + ((lane >> 4) & 1) * 8;

    for (int c = 0; c < NCH; c++) {
        uint4 na0, na1, nb0;
        if (c + 1 < NCH) {
            size_t ao = aoffBase + (size_t)(c + 1) * 32;
            size_t bo = boffBase + (size_t)(c + 1) * 32;
            na0 = *(const uint4*)(Ag + ao);
            na1 = *(const uint4*)(Ag + ao + 8);
            nb0 = *(const uint4*)(Bg + bo);
        }

        uint32_t base = smb + (uint32_t)(c & 1) * STG;
#pragma unroll
        for (int ks = 0; ks < 2; ks++) {
            int sa = ks * 2 + (lane >> 4);
            int sb = ks * 2 + ((lane >> 3) & 1);
            uint32_t ah[2][4];
#pragma unroll
            for (int i = 0; i < 2; i++) {
                int rr = ra + i * 16;
                uint32_t off = (uint32_t)rr * 64 + ((sa ^ ((rr >> 1) & 3)) << 4);
                ldsm4(ah[i], base + off);
            }
            uint32_t bh[4][2];
#pragma unroll
            for (int p = 0; p < 2; p++) {
                int rr = rb + p * 16;
                uint32_t off = (uint32_t)rr * 64 + ((sb ^ ((rr >> 1) & 3)) << 4);
                uint32_t t4[4];
                ldsm4(t4, base + 8192 + off);
                bh[2 * p][0] = t4[0]; bh[2 * p][1] = t4[1];
                bh[2 * p + 1][0] = t4[2]; bh[2 * p + 1][1] = t4[3];
            }
#pragma unroll
            for (int i = 0; i < 2; i++)
#pragma unroll
                for (int j = 0; j < 4; j++)
                    mma_f16(acc[i][j], ah[i], bh[j]);
        }

        if (c + 1 < NCH) {
            char* d = smbuf + ((c + 1) & 1) * STG;
            *(uint4*)(d + asw0) = na0;
            *(uint4*)(d + asw1) = na1;
            *(uint4*)(d + bsw) = nb0;
            __syncthreads();
        }
    }

    // ---------- epilogue: bias + relu + fp16 store + fp32 stats ----------
    float ss0[4], ss1[4], qq0[4], qq1[4];
#pragma unroll
    for (int j = 0; j < 4; j++) { ss0[j] = ss1[j] = qq0[j] = qq1[j] = 0.f; }

    int mb = rowBase + wm * 32 + (lane >> 2);
#pragma unroll
    for (int i = 0; i < 2; i++) {
        int m0 = mb + i * 16;
        int m1 = m0 + 8;
        bool v0 = m0 < NN, v1 = m1 < NN;
        float d0 = s_deg[m0 - rowBase];
        float d1 = s_deg[m1 - rowBase];
#pragma unroll
        for (int j = 0; j < 4; j++) {
            int cl = wn * 32 + j * 8 + (lane & 3) * 2;
            float b0 = s_bias[cl], b1 = s_bias[cl + 1];
            float x0 = fmaxf(acc[i][j][0] + d0 * b0, 0.f);
            float x1 = fmaxf(acc[i][j][1] + d0 * b1, 0.f);
            float x2 = fmaxf(acc[i][j][2] + d1 * b0, 0.f);
            float x3 = fmaxf(acc[i][j][3] + d1 * b1, 0.f);
            if (v0) *(__half2*)&g_hp16[(size_t)m0 * HID + colBase + cl] = __floats2half2_rn(x0, x1);
            if (v1) *(__half2*)&g_hp16[(size_t)m1 * HID + colBase + cl] = __floats2half2_rn(x2, x3);
            float m00 = v0 ? x0 : 0.f, m01 = v0 ? x1 : 0.f;
            float m10 = v1 ? x2 : 0.f, m11 = v1 ? x3 : 0.f;
            ss0[j] += m00 + m10;
            ss1[j] += m01 + m11;
            qq0[j] += m00 * m00 + m10 * m10;
            qq1[j] += m01 * m01 + m11 * m11;
        }
    }
#pragma unroll
    for (int j = 0; j < 4; j++) {
#pragma unroll
        for (int o = 4; o < 32; o <<= 1) {
            ss0[j] += __shfl_xor_sync(0xffffffffu, ss0[j], o);
            ss1[j] += __shfl_xor_sync(0xffffffffu, ss1[j], o);
            qq0[j] += __shfl_xor_sync(0xffffffffu, qq0[j], o);
            qq1[j] += __shfl_xor_sync(0xffffffffu, qq1[j], o);
        }
        if (lane < 4) {
            int cl = wn * 32 + j * 8 + lane * 2;
            atomicAdd(&s_sum[cl], ss0[j]);
            atomicAdd(&s_sum[cl + 1], ss1[j]);
            atomicAdd(&s_sq[cl], qq0[j]);
            atomicAdd(&s_sq[cl + 1], qq1[j]);
        }
    }
    __syncthreads();
    if (tid < 64) {
        atomicAdd(&g_stats3[layer * 512 + colBase + tid], s_sum[tid]);
        atomicAdd(&g_stats3[layer * 512 + HID + colBase + tid], s_sq[tid]);
    }
}

// ---------------- fused layer-3 BN + pooling + MLP ----------------
__device__ __forceinline__ int lower_bound_dev(const int* a, int n, int key) {
    int lo = 0, hi = n;
    while (lo < hi) {
        int m = (lo + hi) >> 1;
        if (a[m] < key) lo = m + 1; else hi = m;
    }
    return lo;
}

__global__ __launch_bounds__(512) void mlp_kernel(const int* __restrict__ batch,
                                                  const float* __restrict__ neighbor,
                                                  const float* __restrict__ g3,
                                                  const float* __restrict__ be3,
                                                  const float* __restrict__ fc1w,
                                                  const float* __restrict__ fc1b,
                                                  const float* __restrict__ fc2w,
                                                  const float* __restrict__ fc2b,
                                                  float* __restrict__ out) {
    const int ZD = HID + 1 + IN_C;  // 385
    __shared__ float z[ZD];
    __shared__ float part[512];
    __shared__ float red[NCO];
    int b = blockIdx.x;
    int t = threadIdx.x;

    int lo = lower_bound_dev(batch, NN, b);
    int hi = lower_bound_dev(batch, NN, b + 1);

    {
        int c = t & 255;
        int half = t >> 8;
        const float invN = 1.0f / (float)NN;
        float mu = g_stats3[2 * 512 + c] * invN;
        float var = g_stats3[2 * 512 + HID + c] * invN - mu * mu;
        float rs = rsqrtf(var + EPSV);
        float sc = g3[c] * rs;
        float off = be3[c] - mu * sc;
        float s = 0.f;
        for (int r = lo + half; r < hi; r += 2)
            s += fmaxf(__half2float(g_hp16[(size_t)r * HID + c]) * sc + off, 0.f);
        part[t] = s;
    }
    __syncthreads();
    if (t < HID) z[t] = part[t] + part[t + 256];
    else if (t == HID) z[HID] = (float)(hi - lo) / MAXSZ;
    else if (t > HID && t < HID + 1 + IN_C + 1) {
        int k = t - HID - 1;
        if (k < IN_C) z[HID + 1 + k] = neighbor[b * IN_C + k];
    }
    if (t < NCO) red[t] = fc2b[t];
    __syncthreads();

    float acc = fc1b[t];
#pragma unroll 4
    for (int k = 0; k < ZD; k++) acc += z[k] * fc1w[k * MLPD + t];
    float h1 = fmaxf(acc, 0.f);

    float4 w4 = *(const float4*)&fc2w[t * NCO];
    float p0 = h1 * w4.x, p1 = h1 * w4.y, p2 = h1 * w4.z, p3 = h1 * w4.w;
#pragma unroll
    for (int o = 16; o >= 1; o >>= 1) {
        p0 += __shfl_xor_sync(0xffffffffu, p0, o);
        p1 += __shfl_xor_sync(0xffffffffu, p1, o);
        p2 += __shfl_xor_sync(0xffffffffu, p2, o);
        p3 += __shfl_xor_sync(0xffffffffu, p3, o);
    }
    if ((t & 31) == 0) {
        atomicAdd(&red[0], p0);
        atomicAdd(&red[1], p1);
        atomicAdd(&red[2], p2);
        atomicAdd(&red[3], p3);
    }
    __syncthreads();
    if (t < NCO) out[b * NCO + t] = red[t];
}

// ---------------- launch ----------------
extern "C" void kernel_launch(void* const* d_in, const int* in_sizes, int n_in,
                              void* d_out, int out_size) {
    const float* x        = (const float*)d_in[0];
    const int*   ei       = (const int*)d_in[1];
    const float* ea       = (const float*)d_in[2];
    const int*   batch    = (const int*)d_in[3];
    const float* neighbor = (const float*)d_in[4];
    const float* W1  = (const float*)d_in[5];
    const float* b1  = (const float*)d_in[6];
    const float* g1  = (const float*)d_in[7];
    const float* be1 = (const float*)d_in[8];
    const float* W2  = (const float*)d_in[9];
    const float* b2  = (const float*)d_in[10];
    const float* g2  = (const float*)d_in[11];
    const float* be2 = (const float*)d_in[12];
    const float* W3  = (const float*)d_in[13];
    const float* b3  = (const float*)d_in[14];
    const float* g3  = (const float*)d_in[15];
    const float* be3 = (const float*)d_in[16];
    const float* fc1w = (const float*)d_in[17];
    const float* fc1b = (const float*)d_in[18];
    const float* fc2w = (const float*)d_in[19];
    const float* fc2b = (const float*)d_in[20];
    float* out = (float*)d_out;

    // init + x16 + W images (NN*IN_C = 1.28M dominates the grid)
    init_kernel<<<(NN * IN_C + 255) / 256, 256>>>(x, W1, W2, W3);
    hist_kernel<<<(EE / 4 + 255) / 256, 256>>>(ei);
    scan_kernel<<<1, 1024>>>();
    fill_kernel<<<(EE / 4 + 255) / 256, 256>>>(ei);

    dim3 gg(4, 79);
    const size_t dsm = 24576;   // 2 x 12K stages

    // layer 1
    aggprep1_kernel<<<NN, 128>>>(ea);
    f16gemm_kernel<K1, 10><<<gg, 256, dsm>>>(0, b1);

    // layer 2
    aggprep23_kernel<true><<<NN, 128>>>(0, g1, be1);
    f16gemm_kernel<K23, 18><<<gg, 256, dsm>>>(1, b2);

    // layer 3
    aggprep23_kernel<false><<<NN, 128>>>(1, g2, be2);
    f16gemm_kernel<K23, 18><<<gg, 256, dsm>>>(2, b3);

    // layer-3 BN + pooling + MLP
    mlp_kernel<<<BB, MLPD>>>(batch, neighbor, g3, be3, fc1w, fc1b, fc2w, fc2b, out);
}

// round 13
// speedup vs baseline: 1.6919x; 1.6259x over previous
#include <cuda_runtime.h>
#include <cuda_bf16.h>
#include <cuda_fp16.h>
#include <cstdint>

// Problem constants
#define NN    10000
#define EE    320000
#define BB    64
#define IN_C  128
#define EC    64
#define HID   256
#define MLPD  512
#define NCO   4
#define K1    320
#define K23   576
#define EPSV  1e-5f
#define MAXSZ 40.0f
#define PADROWS 128
#define LSTR  (HID * K23)   // per-layer B image stride (elements)

// ---------------- scratch ----------------
// g_deg is statically zero-initialized; scan_kernel re-zeroes it after reading,
// so each call's histogram (in init_kernel) starts from zero. Deterministic
// across graph replays.
__device__ int   g_deg[NN];
__device__ int   g_off[NN + 2];
__device__ int   g_cur[NN];
__device__ int   g_src[EE];
__device__ int   g_eid[EE];
__device__ __align__(16) float g_Sea[NN * EC];
__device__ __align__(16) __half g_hp16[NN * HID];  // post-relu pre-BN activation (fp16)
__device__ __align__(16) __half g_x16[NN * IN_C];  // fp16 copy of input features
__device__ float g_stats3[3 * 2 * HID];
__device__ __align__(16) __half g_A16[(NN + PADROWS) * K23];  // fp16 A
__device__ __align__(16) __half g_Bhi[3 * LSTR];  // [layer][n 256][k K] fp16

// ---------------- helpers ----------------
__device__ __forceinline__ uint32_t smem_u32(const void* p) {
    uint32_t a;
    asm("{ .reg .u64 t; cvta.to.shared.u64 t, %1; cvt.u32.u64 %0, t; }" : "=r"(a) : "l"(p));
    return a;
}
__device__ __forceinline__ void ldsm4(uint32_t* r, uint32_t addr) {
    asm volatile("ldmatrix.sync.aligned.m8n8.x4.shared.b16 {%0,%1,%2,%3}, [%4];"
                 : "=r"(r[0]), "=r"(r[1]), "=r"(r[2]), "=r"(r[3]) : "r"(addr));
}
__device__ __forceinline__ void mma_f16(float* c, const uint32_t* a, const uint32_t* b) {
    asm volatile(
        "mma.sync.aligned.m16n8k16.row.col.f32.f16.f16.f32 "
        "{%0,%1,%2,%3}, {%4,%5,%6,%7}, {%8,%9}, {%0,%1,%2,%3};\n"
        : "+f"(c[0]), "+f"(c[1]), "+f"(c[2]), "+f"(c[3])
        : "r"(a[0]), "r"(a[1]), "r"(a[2]), "r"(a[3]), "r"(b[0]), "r"(b[1]));
}

// ---------------- init + x->fp16 + W prep + degree histogram (merged) ----------------
__global__ void init_kernel(const float* __restrict__ x, const float* __restrict__ W1,
                            const float* __restrict__ W2, const float* __restrict__ W3,
                            const int* __restrict__ ei) {
    int i = blockIdx.x * blockDim.x + threadIdx.x;
    if (i < 3 * 2 * HID) g_stats3[i] = 0.f;
    __half z = __float2half(0.f);
    if (i < PADROWS * K1) g_A16[(size_t)NN * K1 + i] = z;
    if (i < PADROWS * K23) g_A16[(size_t)NN * K23 + i] = z;
    if (i < NN * IN_C) g_x16[i] = __float2half_rn(x[i]);
    // degree histogram (g_deg is zero from static init / previous scan reset)
    if (i < EE) atomicAdd(&g_deg[ei[EE + i]], 1);
    // W images: B = W^T, [n][k] k-major
    if (i < HID * K1) {
        int n = i / K1, k = i - n * K1;
        g_Bhi[i] = __float2half_rn(W1[(size_t)k * HID + n]);
    }
    if (i < HID * K23) {
        int n = i / K23, k = i - n * K23;
        g_Bhi[LSTR + i] = __float2half_rn(W2[(size_t)k * HID + n]);
        g_Bhi[2 * LSTR + i] = __float2half_rn(W3[(size_t)k * HID + n]);
    }
}

// ---------------- scan (reads g_deg, then zeroes it for the next call) ----------------
__global__ void scan_kernel() {
    const int CH = 10;
    int tid = threadIdx.x;
    int base = tid * CH;
    int local[CH];
    int s = 0;
#pragma unroll
    for (int i = 0; i < CH; i++) {
        int idx = base + i;
        int v = 0;
        if (idx < NN) {
            v = g_deg[idx];
            g_deg[idx] = 0;  // reset for next call's histogram
        }
        local[i] = s;
        s += v;
    }
    __shared__ int sh[1024];
    sh[tid] = s;
    __syncthreads();
    for (int d = 1; d < 1024; d <<= 1) {
        int t = (tid >= d) ? sh[tid - d] : 0;
        __syncthreads();
        sh[tid] += t;
        __syncthreads();
    }
    int excl = sh[tid] - s;
#pragma unroll
    for (int i = 0; i < CH; i++) {
        int idx = base + i;
        if (idx < NN) {
            int o = excl + local[i];
            g_off[idx] = o;
            g_cur[idx] = o;
        }
    }
    if (tid == 0) { g_off[NN] = EE; g_off[NN + 1] = EE; }
}

__global__ void fill_kernel(const int* __restrict__ ei) {
    int e = (blockIdx.x * blockDim.x + threadIdx.x) * 4;
#pragma unroll
    for (int k = 0; k < 4; k++) {
        int ee = e + k;
        if (ee < EE) {
            int s = ei[ee];
            int d = ei[EE + ee];
            int pos = atomicAdd(&g_cur[d], 1);
            g_src[pos] = s;
            g_eid[pos] = ee;
        }
    }
}

// ---------------- layer-1: x gather (half2, warps 0-1) + ea gather (warps 2-3) ----------------
__global__ void aggprep1_kernel(const float* __restrict__ ea) {
    int v = blockIdx.x;
    int t = threadIdx.x;  // 128
    int s0 = g_off[v], s1 = g_off[v + 1];

    if (t < 64) {
        // gather x as half2: cols [2t, 2t+1]
        const __half2* __restrict__ x2 = (const __half2*)g_x16;  // row stride 64
        float2 f = __half22float2(x2[(size_t)v * 64 + t]);
        float a0 = f.x, a1 = f.y;
        int j = s0;
        for (; j + 4 <= s1; j += 4) {
            int ia = g_src[j], ib = g_src[j + 1], ic = g_src[j + 2], id = g_src[j + 3];
            float2 fa = __half22float2(x2[(size_t)ia * 64 + t]);
            float2 fb = __half22float2(x2[(size_t)ib * 64 + t]);
            float2 fc = __half22float2(x2[(size_t)ic * 64 + t]);
            float2 fd = __half22float2(x2[(size_t)id * 64 + t]);
            a0 += fa.x + fb.x + fc.x + fd.x;
            a1 += fa.y + fb.y + fc.y + fd.y;
        }
        for (; j < s1; j++) {
            float2 fa = __half22float2(x2[(size_t)g_src[j] * 64 + t]);
            a0 += fa.x;
            a1 += fa.y;
        }
        float degf = (float)(s1 - s0 + 1);
        __half2* Arow2 = (__half2*)(g_A16 + (size_t)v * K1);
        Arow2[t] = __floats2half2_rn(degf * f.x, degf * f.y);
        Arow2[64 + t] = __floats2half2_rn(a0, a1);
    } else {
        // gather edge attrs: col c
        int c = t - 64;
        float aea = 1.0f;  // self-loop edge attr = 1.0
        int j = s0;
        for (; j + 4 <= s1; j += 4) {
            int e0 = g_eid[j], e1 = g_eid[j + 1], e2 = g_eid[j + 2], e3 = g_eid[j + 3];
            aea += ea[(size_t)e0 * EC + c] + ea[(size_t)e1 * EC + c] +
                   ea[(size_t)e2 * EC + c] + ea[(size_t)e3 * EC + c];
        }
        for (; j < s1; j++) aea += ea[(size_t)g_eid[j] * EC + c];
        g_Sea[v * EC + c] = aea;
        g_A16[(size_t)v * K1 + 2 * IN_C + c] = __float2half_rn(aea);
    }
}

// ---------------- layers 2/3: fused BN + relu + half2 gather aggregation ----------------
template <bool WRITE_SEA>
__global__ void aggprep23_kernel(int statsLayer, const float* __restrict__ gamma,
                                 const float* __restrict__ beta) {
    int v = blockIdx.x;
    int t = threadIdx.x;  // 128; cols 2t, 2t+1
    int c0 = 2 * t, c1 = c0 + 1;
    const float invN = 1.0f / (float)NN;
    float mu0 = g_stats3[statsLayer * 512 + c0] * invN;
    float var0 = g_stats3[statsLayer * 512 + HID + c0] * invN - mu0 * mu0;
    float sc0 = gamma[c0] * rsqrtf(var0 + EPSV);
    float off0 = beta[c0] - mu0 * sc0;
    float mu1 = g_stats3[statsLayer * 512 + c1] * invN;
    float var1 = g_stats3[statsLayer * 512 + HID + c1] * invN - mu1 * mu1;
    float sc1 = gamma[c1] * rsqrtf(var1 + EPSV);
    float off1 = beta[c1] - mu1 * sc1;

    const __half2* __restrict__ hp2 = (const __half2*)g_hp16;  // row stride 128
    int s0 = g_off[v], s1 = g_off[v + 1];
    float2 f = __half22float2(hp2[(size_t)v * 128 + t]);
    float sv0 = fmaxf(f.x * sc0 + off0, 0.f);
    float sv1 = fmaxf(f.y * sc1 + off1, 0.f);
    float a0 = sv0, a1 = sv1;
    int j = s0;
    for (; j + 4 <= s1; j += 4) {
        int ia = g_src[j], ib = g_src[j + 1], ic = g_src[j + 2], id = g_src[j + 3];
        float2 fa = __half22float2(hp2[(size_t)ia * 128 + t]);
        float2 fb = __half22float2(hp2[(size_t)ib * 128 + t]);
        float2 fc = __half22float2(hp2[(size_t)ic * 128 + t]);
        float2 fd = __half22float2(hp2[(size_t)id * 128 + t]);
        a0 += fmaxf(fa.x * sc0 + off0, 0.f) + fmaxf(fb.x * sc0 + off0, 0.f) +
              fmaxf(fc.x * sc0 + off0, 0.f) + fmaxf(fd.x * sc0 + off0, 0.f);
        a1 += fmaxf(fa.y * sc1 + off1, 0.f) + fmaxf(fb.y * sc1 + off1, 0.f) +
              fmaxf(fc.y * sc1 + off1, 0.f) + fmaxf(fd.y * sc1 + off1, 0.f);
    }
    for (; j < s1; j++) {
        float2 fa = __half22float2(hp2[(size_t)g_src[j] * 128 + t]);
        a0 += fmaxf(fa.x * sc0 + off0, 0.f);
        a1 += fmaxf(fa.y * sc1 + off1, 0.f);
    }

    float degf = (float)(s1 - s0 + 1);
    __half2* Arow2 = (__half2*)(g_A16 + (size_t)v * K23);
    Arow2[t] = __floats2half2_rn(degf * sv0, degf * sv1);
    Arow2[128 + t] = __floats2half2_rn(a0, a1);
    if (WRITE_SEA && t < 32)
        Arow2[256 + t] = __floats2half2_rn(g_Sea[v * EC + 2 * t], g_Sea[v * EC + 2 * t + 1]);
}

// ---------------- fp16 single-pass HMMA GEMM: g_hp16 = relu(A @ W + deg*b), fused fp32 stats ----------------
// BM=128, BN=64, BK=32. 256 threads, warps 4x2 (warp tile 32x32).
// SMEM stage: A 8K | B 4K = 12K, double-buffered = 24K dyn.
// Occupancy 3 CTAs/SM -> 444 slots >= 316 CTAs: single wave (no quantization tail).
template <int K, int NCH>
__global__ __launch_bounds__(256, 3) void f16gemm_kernel(int layer,
                                                         const float* __restrict__ bias) {
    extern __shared__ __align__(16) char smbuf[];
    const int STG = 12288;
    __shared__ float s_bias[64], s_deg[128], s_sum[64], s_sq[64];

    int tid = threadIdx.x;
    int lane = tid & 31;
    int wid = tid >> 5;
    int wm = wid >> 1;   // 0..3
    int wn = wid & 1;    // 0..1
    int rowBase = blockIdx.y * 128;
    int colBase = blockIdx.x * 64;

    if (tid < 128) {
        int r = rowBase + tid;
        s_deg[tid] = (r < NN) ? (float)(g_off[r + 1] - g_off[r] + 1) : 0.f;
    }
    if (tid < 64) {
        s_bias[tid] = bias[colBase + tid];
        s_sum[tid] = 0.f;
        s_sq[tid] = 0.f;
    }

    uint32_t smb = smem_u32(smbuf);

    const __half* __restrict__ Ag = g_A16;
    const __half* __restrict__ Bg = g_Bhi + (size_t)layer * LSTR;

    // A load map: thread -> row = tid/2, 2 segs (16 halves) starting at (tid&1)*16
    int arow = tid >> 1;
    int at2 = tid & 1;
    size_t aoffBase = (size_t)(rowBase + arow) * K + at2 * 16;
    uint32_t asw0 = (uint32_t)arow * 64 + (((at2 * 2) ^ ((arow >> 1) & 3)) << 4);
    uint32_t asw1 = (uint32_t)arow * 64 + (((at2 * 2 + 1) ^ ((arow >> 1) & 3)) << 4);
    // B load map: thread -> row(n) = tid/4, seg = tid&3
    int brow = tid >> 2;
    int bseg = tid & 3;
    size_t boffBase = (size_t)(colBase + brow) * K + bseg * 8;
    uint32_t bsw = 8192u + (uint32_t)brow * 64 + ((bseg ^ ((brow >> 1) & 3)) << 4);

    float acc[2][4][4];
#pragma unroll
    for (int i = 0; i < 2; i++)
#pragma unroll
        for (int j = 0; j < 4; j++)
#pragma unroll
            for (int q = 0; q < 4; q++) acc[i][j][q] = 0.f;

    // prologue: chunk 0 -> buf0
    {
        uint4 a0 = *(const uint4*)(Ag + aoffBase);
        uint4 a1 = *(const uint4*)(Ag + aoffBase + 8);
        uint4 b0 = *(const uint4*)(Bg + boffBase);
        *(uint4*)(smbuf + asw0) = a0;
        *(uint4*)(smbuf + asw1) = a1;
        *(uint4*)(smbuf + bsw) = b0;
    }
    __syncthreads();

    // frag address components
    int ra = wm * 32 + (lane & 7) + ((lane >> 3) & 1) * 8;
    int rb = wn * 32 + (lane & 7) + ((lane >> 4) & 1) * 8;

    for (int c = 0; c < NCH; c++) {
        uint4 na0, na1, nb0;
        if (c + 1 < NCH) {
            size_t ao = aoffBase + (size_t)(c + 1) * 32;
            size_t bo = boffBase + (size_t)(c + 1) * 32;
            na0 = *(const uint4*)(Ag + ao);
            na1 = *(const uint4*)(Ag + ao + 8);
            nb0 = *(const uint4*)(Bg + bo);
        }

        uint32_t base = smb + (uint32_t)(c & 1) * STG;
#pragma unroll
        for (int ks = 0; ks < 2; ks++) {
            int sa = ks * 2 + (lane >> 4);
            int sb = ks * 2 + ((lane >> 3) & 1);
            uint32_t ah[2][4];
#pragma unroll
            for (int i = 0; i < 2; i++) {
                int rr = ra + i * 16;
                uint32_t off = (uint32_t)rr * 64 + ((sa ^ ((rr >> 1) & 3)) << 4);
                ldsm4(ah[i], base + off);
            }
            uint32_t bh[4][2];
#pragma unroll
            for (int p = 0; p < 2; p++) {
                int rr = rb + p * 16;
                uint32_t off = (uint32_t)rr * 64 + ((sb ^ ((rr >> 1) & 3)) << 4);
                uint32_t t4[4];
                ldsm4(t4, base + 8192 + off);
                bh[2 * p][0] = t4[0]; bh[2 * p][1] = t4[1];
                bh[2 * p + 1][0] = t4[2]; bh[2 * p + 1][1] = t4[3];
            }
#pragma unroll
            for (int i = 0; i < 2; i++)
#pragma unroll
                for (int j = 0; j < 4; j++)
                    mma_f16(acc[i][j], ah[i], bh[j]);
        }

        if (c + 1 < NCH) {
            char* d = smbuf + ((c + 1) & 1) * STG;
            *(uint4*)(d + asw0) = na0;
            *(uint4*)(d + asw1) = na1;
            *(uint4*)(d + bsw) = nb0;
            __syncthreads();
        }
    }

    // ---------- epilogue: bias + relu + fp16 store + fp32 stats ----------
    float ss0[4], ss1[4], qq0[4], qq1[4];
#pragma unroll
    for (int j = 0; j < 4; j++) { ss0[j] = ss1[j] = qq0[j] = qq1[j] = 0.f; }

    int mb = rowBase + wm * 32 + (lane >> 2);
#pragma unroll
    for (int i = 0; i < 2; i++) {
        int m0 = mb + i * 16;
        int m1 = m0 + 8;
        bool v0 = m0 < NN, v1 = m1 < NN;
        float d0 = s_deg[m0 - rowBase];
        float d1 = s_deg[m1 - rowBase];
#pragma unroll
        for (int j = 0; j < 4; j++) {
            int cl = wn * 32 + j * 8 + (lane & 3) * 2;
            float b0 = s_bias[cl], b1 = s_bias[cl + 1];
            float x0 = fmaxf(acc[i][j][0] + d0 * b0, 0.f);
            float x1 = fmaxf(acc[i][j][1] + d0 * b1, 0.f);
            float x2 = fmaxf(acc[i][j][2] + d1 * b0, 0.f);
            float x3 = fmaxf(acc[i][j][3] + d1 * b1, 0.f);
            if (v0) *(__half2*)&g_hp16[(size_t)m0 * HID + colBase + cl] = __floats2half2_rn(x0, x1);
            if (v1) *(__half2*)&g_hp16[(size_t)m1 * HID + colBase + cl] = __floats2half2_rn(x2, x3);
            float m00 = v0 ? x0 : 0.f, m01 = v0 ? x1 : 0.f;
            float m10 = v1 ? x2 : 0.f, m11 = v1 ? x3 : 0.f;
            ss0[j] += m00 + m10;
            ss1[j] += m01 + m11;
            qq0[j] += m00 * m00 + m10 * m10;
            qq1[j] += m01 * m01 + m11 * m11;
        }
    }
#pragma unroll
    for (int j = 0; j < 4; j++) {
#pragma unroll
        for (int o = 4; o < 32; o <<= 1) {
            ss0[j] += __shfl_xor_sync(0xffffffffu, ss0[j], o);
            ss1[j] += __shfl_xor_sync(0xffffffffu, ss1[j], o);
            qq0[j] += __shfl_xor_sync(0xffffffffu, qq0[j], o);
            qq1[j] += __shfl_xor_sync(0xffffffffu, qq1[j], o);
        }
        if (lane < 4) {
            int cl = wn * 32 + j * 8 + lane * 2;
            atomicAdd(&s_sum[cl], ss0[j]);
            atomicAdd(&s_sum[cl + 1], ss1[j]);
            atomicAdd(&s_sq[cl], qq0[j]);
            atomicAdd(&s_sq[cl + 1], qq1[j]);
        }
    }
    __syncthreads();
    if (tid < 64) {
        atomicAdd(&g_stats3[layer * 512 + colBase + tid], s_sum[tid]);
        atomicAdd(&g_stats3[layer * 512 + HID + colBase + tid], s_sq[tid]);
    }
}

// ---------------- fused layer-3 BN + pooling + MLP ----------------
__device__ __forceinline__ int lower_bound_dev(const int* a, int n, int key) {
    int lo = 0, hi = n;
    while (lo < hi) {
        int m = (lo + hi) >> 1;
        if (a[m] < key) lo = m + 1; else hi = m;
    }
    return lo;
}

__global__ __launch_bounds__(512) void mlp_kernel(const int* __restrict__ batch,
                                                  const float* __restrict__ neighbor,
                                                  const float* __restrict__ g3,
                                                  const float* __restrict__ be3,
                                                  const float* __restrict__ fc1w,
                                                  const float* __restrict__ fc1b,
                                                  const float* __restrict__ fc2w,
                                                  const float* __restrict__ fc2b,
                                                  float* __restrict__ out) {
    const int ZD = HID + 1 + IN_C;  // 385
    __shared__ float z[ZD];
    __shared__ float part[512];
    __shared__ float red[NCO];
    int b = blockIdx.x;
    int t = threadIdx.x;

    int lo = lower_bound_dev(batch, NN, b);
    int hi = lower_bound_dev(batch, NN, b + 1);

    {
        int c = t & 255;
        int half = t >> 8;
        const float invN = 1.0f / (float)NN;
        float mu = g_stats3[2 * 512 + c] * invN;
        float var = g_stats3[2 * 512 + HID + c] * invN - mu * mu;
        float rs = rsqrtf(var + EPSV);
        float sc = g3[c] * rs;
        float off = be3[c] - mu * sc;
        float s = 0.f;
        for (int r = lo + half; r < hi; r += 2)
            s += fmaxf(__half2float(g_hp16[(size_t)r * HID + c]) * sc + off, 0.f);
        part[t] = s;
    }
    __syncthreads();
    if (t < HID) z[t] = part[t] + part[t + 256];
    else if (t == HID) z[HID] = (float)(hi - lo) / MAXSZ;
    else if (t > HID && t < HID + 1 + IN_C + 1) {
        int k = t - HID - 1;
        if (k < IN_C) z[HID + 1 + k] = neighbor[b * IN_C + k];
    }
    if (t < NCO) red[t] = fc2b[t];
    __syncthreads();

    float acc = fc1b[t];
#pragma unroll 4
    for (int k = 0; k < ZD; k++) acc += z[k] * fc1w[k * MLPD + t];
    float h1 = fmaxf(acc, 0.f);

    float4 w4 = *(const float4*)&fc2w[t * NCO];
    float p0 = h1 * w4.x, p1 = h1 * w4.y, p2 = h1 * w4.z, p3 = h1 * w4.w;
#pragma unroll
    for (int o = 16; o >= 1; o >>= 1) {
        p0 += __shfl_xor_sync(0xffffffffu, p0, o);
        p1 += __shfl_xor_sync(0xffffffffu, p1, o);
        p2 += __shfl_xor_sync(0xffffffffu, p2, o);
        p3 += __shfl_xor_sync(0xffffffffu, p3, o);
    }
    if ((t & 31) == 0) {
        atomicAdd(&red[0], p0);
        atomicAdd(&red[1], p1);
        atomicAdd(&red[2], p2);
        atomicAdd(&red[3], p3);
    }
    __syncthreads();
    if (t < NCO) out[b * NCO + t] = red[t];
}

// ---------------- launch ----------------
extern "C" void kernel_launch(void* const* d_in, const int* in_sizes, int n_in,
                              void* d_out, int out_size) {
    const float* x        = (const float*)d_in[0];
    const int*   ei       = (const int*)d_in[1];
    const float* ea       = (const float*)d_in[2];
    const int*   batch    = (const int*)d_in[3];
    const float* neighbor = (const float*)d_in[4];
    const float* W1  = (const float*)d_in[5];
    const float* b1  = (const float*)d_in[6];
    const float* g1  = (const float*)d_in[7];
    const float* be1 = (const float*)d_in[8];
    const float* W2  = (const float*)d_in[9];
    const float* b2  = (const float*)d_in[10];
    const float* g2  = (const float*)d_in[11];
    const float* be2 = (const float*)d_in[12];
    const float* W3  = (const float*)d_in[13];
    const float* b3  = (const float*)d_in[14];
    const float* g3  = (const float*)d_in[15];
    const float* be3 = (const float*)d_in[16];
    const float* fc1w = (const float*)d_in[17];
    const float* fc1b = (const float*)d_in[18];
    const float* fc2w = (const float*)d_in[19];
    const float* fc2b = (const float*)d_in[20];
    float* out = (float*)d_out;

    // init + x16 + W images + degree histogram (NN*IN_C = 1.28M grid covers all)
    init_kernel<<<(NN * IN_C + 255) / 256, 256>>>(x, W1, W2, W3, ei);
    scan_kernel<<<1, 1024>>>();
    fill_kernel<<<(EE / 4 + 255) / 256, 256>>>(ei);

    dim3 gg(4, 79);
    const size_t dsm = 24576;   // 2 x 12K stages

    // layer 1
    aggprep1_kernel<<<NN, 128>>>(ea);
    f16gemm_kernel<K1, 10><<<gg, 256, dsm>>>(0, b1);

    // layer 2
    aggprep23_kernel<true><<<NN, 128>>>(0, g1, be1);
    f16gemm_kernel<K23, 18><<<gg, 256, dsm>>>(1, b2);

    // layer 3
    aggprep23_kernel<false><<<NN, 128>>>(1, g2, be2);
    f16gemm_kernel<K23, 18><<<gg, 256, dsm>>>(2, b3);

    // layer-3 BN + pooling + MLP
    mlp_kernel<<<BB, MLPD>>>(batch, neighbor, g3, be3, fc1w, fc1b, fc2w, fc2b, out);
}

// round 14
// speedup vs baseline: 1.6943x; 1.0014x over previous
#include <cuda_runtime.h>
#include <cuda_bf16.h>
#include <cuda_fp16.h>
#include <cstdint>

// Problem constants
#define NN    10000
#define EE    320000
#define BB    64
#define IN_C  128
#define EC    64
#define HID   256
#define MLPD  512
#define NCO   4
#define K1    320
#define K23   576
#define EPSV  1e-5f
#define MAXSZ 40.0f
#define PADROWS 128
#define LSTR  (HID * K23)   // per-layer B image stride (elements)

// ---------------- scratch ----------------
// g_deg is statically zero-initialized; scan_kernel re-zeroes it after reading,
// so each call's histogram (in init_kernel) starts from zero.
__device__ int   g_deg[NN];
__device__ int   g_off[NN + 2];
__device__ int   g_cur[NN];
__device__ int   g_src[EE];
__device__ int   g_eid[EE];
__device__ __align__(16) float g_Sea[NN * EC];
__device__ __align__(16) __half g_hp16[NN * HID];  // post-relu pre-BN activation (fp16)
__device__ __align__(16) __half g_x16[NN * IN_C];  // fp16 copy of input features
__device__ float g_stats3[3 * 2 * HID];
__device__ __align__(16) __half g_A16[(NN + PADROWS) * K23];  // fp16 A
__device__ __align__(16) __half g_Bhi[3 * LSTR];  // [layer][n 256][k K] fp16

// ---------------- helpers ----------------
__device__ __forceinline__ uint32_t smem_u32(const void* p) {
    uint32_t a;
    asm("{ .reg .u64 t; cvta.to.shared.u64 t, %1; cvt.u32.u64 %0, t; }" : "=r"(a) : "l"(p));
    return a;
}
__device__ __forceinline__ void ldsm4(uint32_t* r, uint32_t addr) {
    asm volatile("ldmatrix.sync.aligned.m8n8.x4.shared.b16 {%0,%1,%2,%3}, [%4];"
                 : "=r"(r[0]), "=r"(r[1]), "=r"(r[2]), "=r"(r[3]) : "r"(addr));
}
__device__ __forceinline__ void mma_f16(float* c, const uint32_t* a, const uint32_t* b) {
    asm volatile(
        "mma.sync.aligned.m16n8k16.row.col.f32.f16.f16.f32 "
        "{%0,%1,%2,%3}, {%4,%5,%6,%7}, {%8,%9}, {%0,%1,%2,%3};\n"
        : "+f"(c[0]), "+f"(c[1]), "+f"(c[2]), "+f"(c[3])
        : "r"(a[0]), "r"(a[1]), "r"(a[2]), "r"(a[3]), "r"(b[0]), "r"(b[1]));
}

// ---------------- init + x->fp16 + W prep + degree histogram (merged) ----------------
__global__ void init_kernel(const float* __restrict__ x, const float* __restrict__ W1,
                            const float* __restrict__ W2, const float* __restrict__ W3,
                            const int* __restrict__ ei) {
    int i = blockIdx.x * blockDim.x + threadIdx.x;
    if (i < 3 * 2 * HID) g_stats3[i] = 0.f;
    __half z = __float2half(0.f);
    if (i < PADROWS * K1) g_A16[(size_t)NN * K1 + i] = z;
    if (i < PADROWS * K23) g_A16[(size_t)NN * K23 + i] = z;
    if (i < NN * IN_C) g_x16[i] = __float2half_rn(x[i]);
    if (i < EE) atomicAdd(&g_deg[ei[EE + i]], 1);
    if (i < HID * K1) {
        int n = i / K1, k = i - n * K1;
        g_Bhi[i] = __float2half_rn(W1[(size_t)k * HID + n]);
    }
    if (i < HID * K23) {
        int n = i / K23, k = i - n * K23;
        g_Bhi[LSTR + i] = __float2half_rn(W2[(size_t)k * HID + n]);
        g_Bhi[2 * LSTR + i] = __float2half_rn(W3[(size_t)k * HID + n]);
    }
}

// ---------------- scan (reads g_deg, then zeroes it for the next call) ----------------
__global__ void scan_kernel() {
    const int CH = 10;
    int tid = threadIdx.x;
    int base = tid * CH;
    int local[CH];
    int s = 0;
#pragma unroll
    for (int i = 0; i < CH; i++) {
        int idx = base + i;
        int v = 0;
        if (idx < NN) {
            v = g_deg[idx];
            g_deg[idx] = 0;
        }
        local[i] = s;
        s += v;
    }
    __shared__ int sh[1024];
    sh[tid] = s;
    __syncthreads();
    for (int d = 1; d < 1024; d <<= 1) {
        int t = (tid >= d) ? sh[tid - d] : 0;
        __syncthreads();
        sh[tid] += t;
        __syncthreads();
    }
    int excl = sh[tid] - s;
#pragma unroll
    for (int i = 0; i < CH; i++) {
        int idx = base + i;
        if (idx < NN) {
            int o = excl + local[i];
            g_off[idx] = o;
            g_cur[idx] = o;
        }
    }
    if (tid == 0) { g_off[NN] = EE; g_off[NN + 1] = EE; }
}

__global__ void fill_kernel(const int* __restrict__ ei) {
    int e = (blockIdx.x * blockDim.x + threadIdx.x) * 4;
#pragma unroll
    for (int k = 0; k < 4; k++) {
        int ee = e + k;
        if (ee < EE) {
            int s = ei[ee];
            int d = ei[EE + ee];
            int pos = atomicAdd(&g_cur[d], 1);
            g_src[pos] = s;
            g_eid[pos] = ee;
        }
    }
}

// ---------------- layer-1: x gather (half2, warps 0-1) + ea gather (warps 2-3), unroll 8 ----------------
__global__ void aggprep1_kernel(const float* __restrict__ ea) {
    int v = blockIdx.x;
    int t = threadIdx.x;  // 128
    int s0 = g_off[v], s1 = g_off[v + 1];

    if (t < 64) {
        const __half2* __restrict__ x2 = (const __half2*)g_x16;  // row stride 64
        float2 f = __half22float2(x2[(size_t)v * 64 + t]);
        float a0 = f.x, a1 = f.y;
        int j = s0;
        for (; j + 8 <= s1; j += 8) {
            int idx[8];
#pragma unroll
            for (int u = 0; u < 8; u++) idx[u] = g_src[j + u];
            float2 fv[8];
#pragma unroll
            for (int u = 0; u < 8; u++) fv[u] = __half22float2(x2[(size_t)idx[u] * 64 + t]);
#pragma unroll
            for (int u = 0; u < 8; u++) { a0 += fv[u].x; a1 += fv[u].y; }
        }
        for (; j < s1; j++) {
            float2 fa = __half22float2(x2[(size_t)g_src[j] * 64 + t]);
            a0 += fa.x;
            a1 += fa.y;
        }
        float degf = (float)(s1 - s0 + 1);
        __half2* Arow2 = (__half2*)(g_A16 + (size_t)v * K1);
        Arow2[t] = __floats2half2_rn(degf * f.x, degf * f.y);
        Arow2[64 + t] = __floats2half2_rn(a0, a1);
    } else {
        int c = t - 64;
        float aea = 1.0f;  // self-loop edge attr = 1.0
        int j = s0;
        for (; j + 8 <= s1; j += 8) {
            int eid[8];
#pragma unroll
            for (int u = 0; u < 8; u++) eid[u] = g_eid[j + u];
            float ev[8];
#pragma unroll
            for (int u = 0; u < 8; u++) ev[u] = ea[(size_t)eid[u] * EC + c];
#pragma unroll
            for (int u = 0; u < 8; u++) aea += ev[u];
        }
        for (; j < s1; j++) aea += ea[(size_t)g_eid[j] * EC + c];
        g_Sea[v * EC + c] = aea;
        g_A16[(size_t)v * K1 + 2 * IN_C + c] = __float2half_rn(aea);
    }
}

// ---------------- layers 2/3: fused BN + relu + half2 gather aggregation, unroll 8 ----------------
template <bool WRITE_SEA>
__global__ void aggprep23_kernel(int statsLayer, const float* __restrict__ gamma,
                                 const float* __restrict__ beta) {
    int v = blockIdx.x;
    int t = threadIdx.x;  // 128; cols 2t, 2t+1
    int c0 = 2 * t, c1 = c0 + 1;
    const float invN = 1.0f / (float)NN;
    float mu0 = g_stats3[statsLayer * 512 + c0] * invN;
    float var0 = g_stats3[statsLayer * 512 + HID + c0] * invN - mu0 * mu0;
    float sc0 = gamma[c0] * rsqrtf(var0 + EPSV);
    float off0 = beta[c0] - mu0 * sc0;
    float mu1 = g_stats3[statsLayer * 512 + c1] * invN;
    float var1 = g_stats3[statsLayer * 512 + HID + c1] * invN - mu1 * mu1;
    float sc1 = gamma[c1] * rsqrtf(var1 + EPSV);
    float off1 = beta[c1] - mu1 * sc1;

    const __half2* __restrict__ hp2 = (const __half2*)g_hp16;  // row stride 128
    int s0 = g_off[v], s1 = g_off[v + 1];
    float2 f = __half22float2(hp2[(size_t)v * 128 + t]);
    float sv0 = fmaxf(f.x * sc0 + off0, 0.f);
    float sv1 = fmaxf(f.y * sc1 + off1, 0.f);
    float a0 = sv0, a1 = sv1;
    int j = s0;
    for (; j + 8 <= s1; j += 8) {
        int idx[8];
#pragma unroll
        for (int u = 0; u < 8; u++) idx[u] = g_src[j + u];
        float2 fv[8];
#pragma unroll
        for (int u = 0; u < 8; u++) fv[u] = __half22float2(hp2[(size_t)idx[u] * 128 + t]);
#pragma unroll
        for (int u = 0; u < 8; u++) {
            a0 += fmaxf(fv[u].x * sc0 + off0, 0.f);
            a1 += fmaxf(fv[u].y * sc1 + off1, 0.f);
        }
    }
    for (; j < s1; j++) {
        float2 fa = __half22float2(hp2[(size_t)g_src[j] * 128 + t]);
        a0 += fmaxf(fa.x * sc0 + off0, 0.f);
        a1 += fmaxf(fa.y * sc1 + off1, 0.f);
    }

    float degf = (float)(s1 - s0 + 1);
    __half2* Arow2 = (__half2*)(g_A16 + (size_t)v * K23);
    Arow2[t] = __floats2half2_rn(degf * sv0, degf * sv1);
    Arow2[128 + t] = __floats2half2_rn(a0, a1);
    if (WRITE_SEA && t < 32)
        Arow2[256 + t] = __floats2half2_rn(g_Sea[v * EC + 2 * t], g_Sea[v * EC + 2 * t + 1]);
}

// ---------------- fp16 single-pass HMMA GEMM: g_hp16 = relu(A @ W + deg*b), fused fp32 stats ----------------
// BM=128, BN=64, BK=32. 256 threads, warps 4x2 (warp tile 32x32).
// SMEM stage: A 8K | B 4K = 12K, double-buffered = 24K dyn.
// Occupancy 3 CTAs/SM -> 444 slots >= 316 CTAs: single wave.
template <int K, int NCH>
__global__ __launch_bounds__(256, 3) void f16gemm_kernel(int layer,
                                                         const float* __restrict__ bias) {
    extern __shared__ __align__(16) char smbuf[];
    const int STG = 12288;
    __shared__ float s_bias[64], s_deg[128], s_sum[64], s_sq[64];

    int tid = threadIdx.x;
    int lane = tid & 31;
    int wid = tid >> 5;
    int wm = wid >> 1;   // 0..3
    int wn = wid & 1;    // 0..1
    int rowBase = blockIdx.y * 128;
    int colBase = blockIdx.x * 64;

    if (tid < 128) {
        int r = rowBase + tid;
        s_deg[tid] = (r < NN) ? (float)(g_off[r + 1] - g_off[r] + 1) : 0.f;
    }
    if (tid < 64) {
        s_bias[tid] = bias[colBase + tid];
        s_sum[tid] = 0.f;
        s_sq[tid] = 0.f;
    }

    uint32_t smb = smem_u32(smbuf);

    const __half* __restrict__ Ag = g_A16;
    const __half* __restrict__ Bg = g_Bhi + (size_t)layer * LSTR;

    int arow = tid >> 1;
    int at2 = tid & 1;
    size_t aoffBase = (size_t)(rowBase + arow) * K + at2 * 16;
    uint32_t asw0 = (uint32_t)arow * 64 + (((at2 * 2) ^ ((arow >> 1) & 3)) << 4);
    uint32_t asw1 = (uint32_t)arow * 64 + (((at2 * 2 + 1) ^ ((arow >> 1) & 3)) << 4);
    int brow = tid >> 2;
    int bseg = tid & 3;
    size_t boffBase = (size_t)(colBase + brow) * K + bseg * 8;
    uint32_t bsw = 8192u + (uint32_t)brow * 64 + ((bseg ^ ((brow >> 1) & 3)) << 4);

    float acc[2][4][4];
#pragma unroll
    for (int i = 0; i < 2; i++)
#pragma unroll
        for (int j = 0; j < 4; j++)
#pragma unroll
            for (int q = 0; q < 4; q++) acc[i][j][q] = 0.f;

    {
        uint4 a0 = *(const uint4*)(Ag + aoffBase);
        uint4 a1 = *(const uint4*)(Ag + aoffBase + 8);
        uint4 b0 = *(const uint4*)(Bg + boffBase);
        *(uint4*)(smbuf + asw0) = a0;
        *(uint4*)(smbuf + asw1) = a1;
        *(uint4*)(smbuf + bsw) = b0;
    }
    __syncthreads();

    int ra = wm * 32 + (lane & 7) + ((lane >> 3) & 1) * 8;
    int rb = wn * 32 + (lane & 7) + ((lane >> 4) & 1) * 8;

    for (int c = 0; c < NCH; c++) {
        uint4 na0, na1, nb0;
        if (c + 1 < NCH) {
            size_t ao = aoffBase + (size_t)(c + 1) * 32;
            size_t bo = boffBase + (size_t)(c + 1) * 32;
            na0 = *(const uint4*)(Ag + ao);
            na1 = *(const uint4*)(Ag + ao + 8);
            nb0 = *(const uint4*)(Bg + bo);
        }

        uint32_t base = smb + (uint32_t)(c & 1) * STG;
#pragma unroll
        for (int ks = 0; ks < 2; ks++) {
            int sa = ks * 2 + (lane >> 4);
            int sb = ks * 2 + ((lane >> 3) & 1);
            uint32_t ah[2][4];
#pragma unroll
            for (int i = 0; i < 2; i++) {
                int rr = ra + i * 16;
                uint32_t off = (uint32_t)rr * 64 + ((sa ^ ((rr >> 1) & 3)) << 4);
                ldsm4(ah[i], base + off);
            }
            uint32_t bh[4][2];
#pragma unroll
            for (int p = 0; p < 2; p++) {
                int rr = rb + p * 16;
                uint32_t off = (uint32_t)rr * 64 + ((sb ^ ((rr >> 1) & 3)) << 4);
                uint32_t t4[4];
                ldsm4(t4, base + 8192 + off);
                bh[2 * p][0] = t4[0]; bh[2 * p][1] = t4[1];
                bh[2 * p + 1][0] = t4[2]; bh[2 * p + 1][1] = t4[3];
            }
#pragma unroll
            for (int i = 0; i < 2; i++)
#pragma unroll
                for (int j = 0; j < 4; j++)
                    mma_f16(acc[i][j], ah[i], bh[j]);
        }

        if (c + 1 < NCH) {
            char* d = smbuf + ((c + 1) & 1) * STG;
            *(uint4*)(d + asw0) = na0;
            *(uint4*)(d + asw1) = na1;
            *(uint4*)(d + bsw) = nb0;
            __syncthreads();
        }
    }

    // ---------- epilogue: bias + relu + fp16 store + fp32 stats ----------
    float ss0[4], ss1[4], qq0[4], qq1[4];
#pragma unroll
    for (int j = 0; j < 4; j++) { ss0[j] = ss1[j] = qq0[j] = qq1[j] = 0.f; }

    int mb = rowBase + wm * 32 + (lane >> 2);
#pragma unroll
    for (int i = 0; i < 2; i++) {
        int m0 = mb + i * 16;
        int m1 = m0 + 8;
        bool v0 = m0 < NN, v1 = m1 < NN;
        float d0 = s_deg[m0 - rowBase];
        float d1 = s_deg[m1 - rowBase];
#pragma unroll
        for (int j = 0; j < 4; j++) {
            int cl = wn * 32 + j * 8 + (lane & 3) * 2;
            float b0 = s_bias[cl], b1 = s_bias[cl + 1];
            float x0 = fmaxf(acc[i][j][0] + d0 * b0, 0.f);
            float x1 = fmaxf(acc[i][j][1] + d0 * b1, 0.f);
            float x2 = fmaxf(acc[i][j][2] + d1 * b0, 0.f);
            float x3 = fmaxf(acc[i][j][3] + d1 * b1, 0.f);
            if (v0) *(__half2*)&g_hp16[(size_t)m0 * HID + colBase + cl] = __floats2half2_rn(x0, x1);
            if (v1) *(__half2*)&g_hp16[(size_t)m1 * HID + colBase + cl] = __floats2half2_rn(x2, x3);
            float m00 = v0 ? x0 : 0.f, m01 = v0 ? x1 : 0.f;
            float m10 = v1 ? x2 : 0.f, m11 = v1 ? x3 : 0.f;
            ss0[j] += m00 + m10;
            ss1[j] += m01 + m11;
            qq0[j] += m00 * m00 + m10 * m10;
            qq1[j] += m01 * m01 + m11 * m11;
        }
    }
#pragma unroll
    for (int j = 0; j < 4; j++) {
#pragma unroll
        for (int o = 4; o < 32; o <<= 1) {
            ss0[j] += __shfl_xor_sync(0xffffffffu, ss0[j], o);
            ss1[j] += __shfl_xor_sync(0xffffffffu, ss1[j], o);
            qq0[j] += __shfl_xor_sync(0xffffffffu, qq0[j], o);
            qq1[j] += __shfl_xor_sync(0xffffffffu, qq1[j], o);
        }
        if (lane < 4) {
            int cl = wn * 32 + j * 8 + lane * 2;
            atomicAdd(&s_sum[cl], ss0[j]);
            atomicAdd(&s_sum[cl + 1], ss1[j]);
            atomicAdd(&s_sq[cl], qq0[j]);
            atomicAdd(&s_sq[cl + 1], qq1[j]);
        }
    }
    __syncthreads();
    if (tid < 64) {
        atomicAdd(&g_stats3[layer * 512 + colBase + tid], s_sum[tid]);
        atomicAdd(&g_stats3[layer * 512 + HID + colBase + tid], s_sq[tid]);
    }
}

// ---------------- fused layer-3 BN + pooling + MLP ----------------
__device__ __forceinline__ int lower_bound_dev(const int* a, int n, int key) {
    int lo = 0, hi = n;
    while (lo < hi) {
        int m = (lo + hi) >> 1;
        if (a[m] < key) lo = m + 1; else hi = m;
    }
    return lo;
}

__global__ __launch_bounds__(512) void mlp_kernel(const int* __restrict__ batch,
                                                  const float* __restrict__ neighbor,
                                                  const float* __restrict__ g3,
                                                  const float* __restrict__ be3,
                                                  const float* __restrict__ fc1w,
                                                  const float* __restrict__ fc1b,
                                                  const float* __restrict__ fc2w,
                                                  const float* __restrict__ fc2b,
                                                  float* __restrict__ out) {
    const int ZD = HID + 1 + IN_C;  // 385
    __shared__ float z[ZD];
    __shared__ float part[512];
    __shared__ float red[NCO];
    int b = blockIdx.x;
    int t = threadIdx.x;

    int lo = lower_bound_dev(batch, NN, b);
    int hi = lower_bound_dev(batch, NN, b + 1);

    {
        int c = t & 255;
        int half = t >> 8;
        const float invN = 1.0f / (float)NN;
        float mu = g_stats3[2 * 512 + c] * invN;
        float var = g_stats3[2 * 512 + HID + c] * invN - mu * mu;
        float rs = rsqrtf(var + EPSV);
        float sc = g3[c] * rs;
        float off = be3[c] - mu * sc;
        float s = 0.f;
        for (int r = lo + half; r < hi; r += 2)
            s += fmaxf(__half2float(g_hp16[(size_t)r * HID + c]) * sc + off, 0.f);
        part[t] = s;
    }
    __syncthreads();
    if (t < HID) z[t] = part[t] + part[t + 256];
    else if (t == HID) z[HID] = (float)(hi - lo) / MAXSZ;
    else if (t > HID && t < HID + 1 + IN_C + 1) {
        int k = t - HID - 1;
        if (k < IN_C) z[HID + 1 + k] = neighbor[b * IN_C + k];
    }
    if (t < NCO) red[t] = fc2b[t];
    __syncthreads();

    float acc = fc1b[t];
#pragma unroll 4
    for (int k = 0; k < ZD; k++) acc += z[k] * fc1w[k * MLPD + t];
    float h1 = fmaxf(acc, 0.f);

    float4 w4 = *(const float4*)&fc2w[t * NCO];
    float p0 = h1 * w4.x, p1 = h1 * w4.y, p2 = h1 * w4.z, p3 = h1 * w4.w;
#pragma unroll
    for (int o = 16; o >= 1; o >>= 1) {
        p0 += __shfl_xor_sync(0xffffffffu, p0, o);
        p1 += __shfl_xor_sync(0xffffffffu, p1, o);
        p2 += __shfl_xor_sync(0xffffffffu, p2, o);
        p3 += __shfl_xor_sync(0xffffffffu, p3, o);
    }
    if ((t & 31) == 0) {
        atomicAdd(&red[0], p0);
        atomicAdd(&red[1], p1);
        atomicAdd(&red[2], p2);
        atomicAdd(&red[3], p3);
    }
    __syncthreads();
    if (t < NCO) out[b * NCO + t] = red[t];
}

// ---------------- launch ----------------
extern "C" void kernel_launch(void* const* d_in, const int* in_sizes, int n_in,
                              void* d_out, int out_size) {
    const float* x        = (const float*)d_in[0];
    const int*   ei       = (const int*)d_in[1];
    const float* ea       = (const float*)d_in[2];
    const int*   batch    = (const int*)d_in[3];
    const float* neighbor = (const float*)d_in[4];
    const float* W1  = (const float*)d_in[5];
    const float* b1  = (const float*)d_in[6];
    const float* g1  = (const float*)d_in[7];
    const float* be1 = (const float*)d_in[8];
    const float* W2  = (const float*)d_in[9];
    const float* b2  = (const float*)d_in[10];
    const float* g2  = (const float*)d_in[11];
    const float* be2 = (const float*)d_in[12];
    const float* W3  = (const float*)d_in[13];
    const float* b3  = (const float*)d_in[14];
    const float* g3  = (const float*)d_in[15];
    const float* be3 = (const float*)d_in[16];
    const float* fc1w = (const float*)d_in[17];
    const float* fc1b = (const float*)d_in[18];
    const float* fc2w = (const float*)d_in[19];
    const float* fc2b = (const float*)d_in[20];
    float* out = (float*)d_out;

    init_kernel<<<(NN * IN_C + 255) / 256, 256>>>(x, W1, W2, W3, ei);
    scan_kernel<<<1, 1024>>>();
    fill_kernel<<<(EE / 4 + 255) / 256, 256>>>(ei);

    dim3 gg(4, 79);
    const size_t dsm = 24576;   // 2 x 12K stages

    // layer 1
    aggprep1_kernel<<<NN, 128>>>(ea);
    f16gemm_kernel<K1, 10><<<gg, 256, dsm>>>(0, b1);

    // layer 2
    aggprep23_kernel<true><<<NN, 128>>>(0, g1, be1);
    f16gemm_kernel<K23, 18><<<gg, 256, dsm>>>(1, b2);

    // layer 3
    aggprep23_kernel<false><<<NN, 128>>>(1, g2, be2);
    f16gemm_kernel<K23, 18><<<gg, 256, dsm>>>(2, b3);

    // layer-3 BN + pooling + MLP
    mlp_kernel<<<BB, MLPD>>>(batch, neighbor, g3, be3, fc1w, fc1b, fc2w, fc2b, out);
}